// round 3
// baseline (speedup 1.0000x reference)
#include <cuda_runtime.h>
#include <cuda_bf16.h>
#include <cstdint>

// Problem constants (fixed by the reference)
constexpr int N_   = 50000;
constexpr int E_   = 800000;
constexpr int EP_  = E_ + N_;      // edges + self loops = 850000
constexpr int C_   = 128;          // feature dim (HEADS*HID)
constexpr int H_   = 4;            // heads
constexpr int HID_ = 32;
constexpr int B_   = 100;
constexpr int NF_  = 15;
constexpr float NEG_SLOPE = 0.2f;

// ---------------- scratch (static device globals; no allocation) ----------------
__device__ __align__(16) float g_xh[(size_t)N_ * C_];   // transformed features [N,128]
__device__ __align__(16) float g_agg[(size_t)N_ * C_];  // aggregation buffer / hidden h
__device__ __align__(16) float g_asrc[N_ * H_];
__device__ __align__(16) float g_adst[N_ * H_];
__device__ __align__(16) float g_emax[N_ * H_];
__device__ __align__(16) float g_denom[N_ * H_];
__device__ int   g_src[EP_];
__device__ int   g_dst[EP_];
__device__ float g_pool[B_ * HID_];
__device__ float g_cnt[B_];

// ---------------- helpers ----------------
__device__ __forceinline__ float lrelu(float x) {
    return x > 0.f ? x : NEG_SLOPE * x;
}

__device__ __forceinline__ void atomicMaxF(float* addr, float v) {
    if (v >= 0.f) atomicMax((int*)addr, __float_as_int(v));
    else          atomicMin((unsigned int*)addr, __float_as_uint(v));
}

// ---------------- kernels ----------------

// Build src/dst with self loops appended. edge_index is INT32 (JAX x64 disabled).
__global__ void k_build_edges(const int* __restrict__ ei) {
    int e = blockIdx.x * blockDim.x + threadIdx.x;
    if (e >= EP_) return;
    if (e < E_) {
        g_src[e] = ei[e];
        g_dst[e] = ei[E_ + e];
    } else {
        g_src[e] = e - E_;
        g_dst[e] = e - E_;
    }
}

// Zero agg, init emax=-inf, denom=0.
__global__ void k_init_layer() {
    int i = blockIdx.x * blockDim.x + threadIdx.x;
    if (i < N_ * C_) g_agg[i] = 0.f;
    if (i < N_ * H_) {
        g_emax[i]  = __int_as_float(0xff800000); // -inf
        g_denom[i] = 0.f;
    }
}

__global__ void k_zero_pool() {
    int i = blockIdx.x * blockDim.x + threadIdx.x;
    if (i < B_ * HID_) g_pool[i] = 0.f;
    if (i < B_)        g_cnt[i]  = 0.f;
}

// xh = X @ W ; a_src/a_dst attention dots. 16 rows/block, 128 threads (thread=out col).
// X==nullptr means "use g_agg as input" (layer 2).
__global__ void __launch_bounds__(128) k_gemm_attn(
    const float* __restrict__ X,
    const float* __restrict__ W,
    const float* __restrict__ attS,
    const float* __restrict__ attD)
{
    __shared__ float xs[16 * 128];
    const float* Xp = X ? X : g_agg;
    int row0 = blockIdx.x * 16;
    int tid  = threadIdx.x;

    const float* xb = Xp + (size_t)row0 * C_;
    #pragma unroll
    for (int r = 0; r < 16; r++) xs[r * 128 + tid] = xb[r * 128 + tid];
    __syncthreads();

    float acc[16];
    #pragma unroll
    for (int r = 0; r < 16; r++) acc[r] = 0.f;

    for (int k = 0; k < 128; k++) {
        float wv = W[k * 128 + tid];
        #pragma unroll
        for (int r = 0; r < 16; r++) acc[r] += xs[r * 128 + k] * wv;
    }

    #pragma unroll
    for (int r = 0; r < 16; r++)
        g_xh[(size_t)(row0 + r) * C_ + tid] = acc[r];

    // attention dot products: warp w == head w, lane == channel
    int head = tid >> 5, lane = tid & 31;
    float as = attS[head * 32 + lane];
    float ad = attD[head * 32 + lane];
    #pragma unroll
    for (int r = 0; r < 16; r++) {
        float vs = acc[r] * as;
        float vd = acc[r] * ad;
        #pragma unroll
        for (int o = 16; o > 0; o >>= 1) {
            vs += __shfl_down_sync(0xffffffffu, vs, o);
            vd += __shfl_down_sync(0xffffffffu, vd, o);
        }
        if (lane == 0) {
            g_asrc[(row0 + r) * H_ + head] = vs;
            g_adst[(row0 + r) * H_ + head] = vd;
        }
    }
}

// Pass 1: per-dst per-head running max of leaky_relu(a_src[src]+a_dst[dst]).
__global__ void k_edge_max() {
    int e = blockIdx.x * blockDim.x + threadIdx.x;
    if (e >= EP_) return;
    int s = g_src[e], d = g_dst[e];
    float4 as4 = *(const float4*)&g_asrc[s * H_];
    float4 ad4 = *(const float4*)&g_adst[d * H_];
    atomicMaxF(&g_emax[d * H_ + 0], lrelu(as4.x + ad4.x));
    atomicMaxF(&g_emax[d * H_ + 1], lrelu(as4.y + ad4.y));
    atomicMaxF(&g_emax[d * H_ + 2], lrelu(as4.z + ad4.z));
    atomicMaxF(&g_emax[d * H_ + 3], lrelu(as4.w + ad4.w));
}

// Pass 2: denom[dst] += exp(e - emax[dst]).
__global__ void k_edge_sum() {
    int e = blockIdx.x * blockDim.x + threadIdx.x;
    if (e >= EP_) return;
    int s = g_src[e], d = g_dst[e];
    float4 as4 = *(const float4*)&g_asrc[s * H_];
    float4 ad4 = *(const float4*)&g_adst[d * H_];
    float4 mx4 = *(const float4*)&g_emax[d * H_];
    atomicAdd(&g_denom[d * H_ + 0], __expf(lrelu(as4.x + ad4.x) - mx4.x));
    atomicAdd(&g_denom[d * H_ + 1], __expf(lrelu(as4.y + ad4.y) - mx4.y));
    atomicAdd(&g_denom[d * H_ + 2], __expf(lrelu(as4.z + ad4.z) - mx4.z));
    atomicAdd(&g_denom[d * H_ + 3], __expf(lrelu(as4.w + ad4.w) - mx4.w));
}

// Pass 3: agg[dst] += alpha * xh[src].  One warp per edge; lane handles 4 floats.
__global__ void k_edge_agg() {
    int t = blockIdx.x * blockDim.x + threadIdx.x;
    int e = t >> 5;
    if (e >= EP_) return;
    int lane = t & 31;
    int s = g_src[e], d = g_dst[e];
    int head = lane >> 3;               // (lane*4)/32

    float asv = g_asrc[s * H_ + head];
    float adv = g_adst[d * H_ + head];
    float mx  = g_emax[d * H_ + head];
    float dn  = g_denom[d * H_ + head];
    float a   = __expf(lrelu(asv + adv) - mx) / (dn + 1e-16f);

    float4 xv = *(const float4*)&g_xh[(size_t)s * C_ + lane * 4];
    float4 v  = make_float4(a * xv.x, a * xv.y, a * xv.z, a * xv.w);
    atomicAdd((float4*)&g_agg[(size_t)d * C_ + lane * 4], v);
}

// h = relu(agg + b1)  (layer 1 epilogue, in place)
__global__ void k_relu_bias(const float* __restrict__ b1) {
    int i = blockIdx.x * blockDim.x + threadIdx.x;
    if (i >= N_ * C_) return;
    g_agg[i] = fmaxf(g_agg[i] + b1[i & 127], 0.f);
}

// Layer-2 epilogue fused with pooling: per-node head-mean + b2, atomic into graph sums.
__global__ void k_pool(const int* __restrict__ batch,
                       const float* __restrict__ b2)
{
    int t = blockIdx.x * blockDim.x + threadIdx.x;
    if (t >= N_ * HID_) return;
    int n = t >> 5, c = t & 31;
    const float* row = &g_agg[(size_t)n * C_];
    float v = 0.25f * (row[c] + row[32 + c] + row[64 + c] + row[96 + c]) + b2[c];
    int b = batch[n];
    atomicAdd(&g_pool[b * HID_ + c], v);
    if (c == 0) atomicAdd(&g_cnt[b], 1.f);
}

// Final MLP: one warp per graph. [32 pooled | 15 stats] -> 32 -> 1
__global__ void k_mlp(const float* __restrict__ stats,
                      const float* __restrict__ Wm1, const float* __restrict__ bm1,
                      const float* __restrict__ Wm2, const float* __restrict__ bm2,
                      float* __restrict__ out)
{
    int b = blockIdx.x;
    int t = threadIdx.x;
    __shared__ float gv[HID_ + NF_ + 1];
    float cnt = fmaxf(g_cnt[b], 1.f);
    gv[t] = g_pool[b * HID_ + t] / cnt;
    if (t < NF_) gv[HID_ + t] = stats[b * NF_ + t];
    __syncwarp();
    float h = bm1[t];
    #pragma unroll
    for (int i = 0; i < HID_ + NF_; i++) h += gv[i] * Wm1[i * HID_ + t];
    h = fmaxf(h, 0.f);
    float o = h * Wm2[t];
    #pragma unroll
    for (int off = 16; off > 0; off >>= 1) o += __shfl_down_sync(0xffffffffu, o, off);
    if (t == 0) out[b] = o + bm2[0];
}

// ---------------- launch ----------------
extern "C" void kernel_launch(void* const* d_in, const int* in_sizes, int n_in,
                              void* d_out, int out_size)
{
    const float* x     = (const float*)d_in[0];
    const int*   ei    = (const int*)d_in[1];      // int32 (JAX x64 disabled)
    const int*   batch = (const int*)d_in[2];      // int32
    const float* stats = (const float*)d_in[3];
    const float* W1    = (const float*)d_in[4];
    const float* as1   = (const float*)d_in[5];
    const float* ad1   = (const float*)d_in[6];
    const float* b1    = (const float*)d_in[7];
    const float* W2    = (const float*)d_in[8];
    const float* as2   = (const float*)d_in[9];
    const float* ad2   = (const float*)d_in[10];
    const float* b2    = (const float*)d_in[11];
    const float* Wm1   = (const float*)d_in[12];
    const float* bm1   = (const float*)d_in[13];
    const float* Wm2   = (const float*)d_in[14];
    const float* bm2   = (const float*)d_in[15];
    float*       out   = (float*)d_out;

    const int T = 256;
    auto cdiv = [](long long a, long long b) { return (int)((a + b - 1) / b); };

    k_build_edges<<<cdiv(EP_, T), T>>>(ei);

    // ---- layer 1 ----
    k_init_layer<<<cdiv((long long)N_ * C_, T), T>>>();
    k_gemm_attn<<<N_ / 16, 128>>>(x, W1, as1, ad1);
    k_edge_max<<<cdiv(EP_, T), T>>>();
    k_edge_sum<<<cdiv(EP_, T), T>>>();
    k_edge_agg<<<cdiv((long long)EP_ * 32, T), T>>>();
    k_relu_bias<<<cdiv((long long)N_ * C_, T), T>>>(b1);

    // ---- layer 2 (gemm reads g_agg, so it runs BEFORE re-init) ----
    k_gemm_attn<<<N_ / 16, 128>>>(nullptr, W2, as2, ad2);
    k_init_layer<<<cdiv((long long)N_ * C_, T), T>>>();
    k_edge_max<<<cdiv(EP_, T), T>>>();
    k_edge_sum<<<cdiv(EP_, T), T>>>();
    k_edge_agg<<<cdiv((long long)EP_ * 32, T), T>>>();

    // ---- pooling + MLP ----
    k_zero_pool<<<cdiv(B_ * HID_ + B_, T), T>>>();
    k_pool<<<cdiv((long long)N_ * HID_, T), T>>>(batch, b2);
    k_mlp<<<B_, HID_>>>(stats, Wm1, bm1, Wm2, bm2, out);
}

// round 4
// speedup vs baseline: 1.2620x; 1.2620x over previous
#include <cuda_runtime.h>
#include <cuda_bf16.h>
#include <cstdint>

// Problem constants (fixed by the reference)
constexpr int N_   = 50000;
constexpr int E_   = 800000;
constexpr int EP_  = E_ + N_;      // edges + self loops = 850000
constexpr int C_   = 128;          // feature dim (HEADS*HID)
constexpr int H_   = 4;            // heads
constexpr int HID_ = 32;
constexpr int B_   = 100;
constexpr int NF_  = 15;
constexpr float NEG_SLOPE = 0.2f;

// ---------------- scratch (static device globals; no allocation) ----------------
__device__ __align__(16) float g_xh[(size_t)N_ * C_];   // transformed features [N,128]
__device__ __align__(16) float g_agg[(size_t)N_ * C_];  // unnormalized aggregation / hidden h
__device__ __align__(16) float g_asrc[N_ * H_];
__device__ __align__(16) float g_adst[N_ * H_];
__device__ __align__(16) float g_denom[N_ * H_];
__device__ int   g_src[EP_];
__device__ int   g_dst[EP_];
__device__ float g_pool[B_ * HID_];
__device__ float g_cnt[B_];

// ---------------- helpers ----------------
__device__ __forceinline__ float lrelu(float x) {
    return x > 0.f ? x : NEG_SLOPE * x;
}

// ---------------- kernels ----------------

// Build src/dst with self loops appended. edge_index is INT32 (JAX x64 disabled).
__global__ void k_build_edges(const int* __restrict__ ei) {
    int e = blockIdx.x * blockDim.x + threadIdx.x;
    if (e >= EP_) return;
    if (e < E_) {
        g_src[e] = ei[e];
        g_dst[e] = ei[E_ + e];
    } else {
        g_src[e] = e - E_;
        g_dst[e] = e - E_;
    }
}

// Zero agg and denom.
__global__ void k_init_layer() {
    int i = blockIdx.x * blockDim.x + threadIdx.x;
    if (i < N_ * C_) g_agg[i] = 0.f;
    if (i < N_ * H_) g_denom[i] = 0.f;
}

__global__ void k_zero_pool() {
    int i = blockIdx.x * blockDim.x + threadIdx.x;
    if (i < B_ * HID_) g_pool[i] = 0.f;
    if (i < B_)        g_cnt[i]  = 0.f;
}

// xh = X @ W ; a_src/a_dst attention dots. 16 rows/block, 128 threads (thread=out col).
// X==nullptr means "use g_agg as input" (layer 2).
__global__ void __launch_bounds__(128) k_gemm_attn(
    const float* __restrict__ X,
    const float* __restrict__ W,
    const float* __restrict__ attS,
    const float* __restrict__ attD)
{
    __shared__ float xs[16 * 128];
    const float* Xp = X ? X : g_agg;
    int row0 = blockIdx.x * 16;
    int tid  = threadIdx.x;

    const float* xb = Xp + (size_t)row0 * C_;
    #pragma unroll
    for (int r = 0; r < 16; r++) xs[r * 128 + tid] = xb[r * 128 + tid];
    __syncthreads();

    float acc[16];
    #pragma unroll
    for (int r = 0; r < 16; r++) acc[r] = 0.f;

    for (int k = 0; k < 128; k++) {
        float wv = W[k * 128 + tid];
        #pragma unroll
        for (int r = 0; r < 16; r++) acc[r] += xs[r * 128 + k] * wv;
    }

    #pragma unroll
    for (int r = 0; r < 16; r++)
        g_xh[(size_t)(row0 + r) * C_ + tid] = acc[r];

    // attention dot products: warp w == head w, lane == channel
    int head = tid >> 5, lane = tid & 31;
    float as = attS[head * 32 + lane];
    float ad = attD[head * 32 + lane];
    #pragma unroll
    for (int r = 0; r < 16; r++) {
        float vs = acc[r] * as;
        float vd = acc[r] * ad;
        #pragma unroll
        for (int o = 16; o > 0; o >>= 1) {
            vs += __shfl_down_sync(0xffffffffu, vs, o);
            vd += __shfl_down_sync(0xffffffffu, vd, o);
        }
        if (lane == 0) {
            g_asrc[(row0 + r) * H_ + head] = vs;
            g_adst[(row0 + r) * H_ + head] = vd;
        }
    }
}

// Fused edge pass: unnormalized softmax-weighted aggregation + denom in ONE pass.
// Softmax is shift-invariant and logits are tiny (|e| < ~10), so no max pass needed.
// One warp per edge; lane handles 4 floats; lanes {0,8,16,24} also add denom.
__global__ void k_edge_fused() {
    int t = blockIdx.x * blockDim.x + threadIdx.x;
    int e = t >> 5;
    if (e >= EP_) return;
    int lane = t & 31;
    int s = g_src[e], d = g_dst[e];
    int head = lane >> 3;               // (lane*4)/32

    float ex = __expf(lrelu(g_asrc[s * H_ + head] + g_adst[d * H_ + head]));

    float4 xv = *(const float4*)&g_xh[(size_t)s * C_ + lane * 4];
    float4 v  = make_float4(ex * xv.x, ex * xv.y, ex * xv.z, ex * xv.w);
    atomicAdd((float4*)&g_agg[(size_t)d * C_ + lane * 4], v);
    if ((lane & 7) == 0) atomicAdd(&g_denom[d * H_ + head], ex);
}

// Layer-1 epilogue: h = relu(agg/denom + b1), per-head normalization, in place.
__global__ void k_norm_relu_bias(const float* __restrict__ b1) {
    int i = blockIdx.x * blockDim.x + threadIdx.x;
    if (i >= N_ * C_) return;
    int c = i & 127;
    int n = i >> 7;
    float dn = g_denom[n * H_ + (c >> 5)] + 1e-16f;
    g_agg[i] = fmaxf(g_agg[i] / dn + b1[c], 0.f);
}

// Layer-2 epilogue fused with pooling: normalize, head-mean + b2, atomic into graph sums.
__global__ void k_pool(const int* __restrict__ batch,
                       const float* __restrict__ b2)
{
    int t = blockIdx.x * blockDim.x + threadIdx.x;
    if (t >= N_ * HID_) return;
    int n = t >> 5, c = t & 31;
    const float* row = &g_agg[(size_t)n * C_];
    const float* dn  = &g_denom[n * H_];
    float v = 0.25f * (row[c]      / (dn[0] + 1e-16f) +
                       row[32 + c] / (dn[1] + 1e-16f) +
                       row[64 + c] / (dn[2] + 1e-16f) +
                       row[96 + c] / (dn[3] + 1e-16f)) + b2[c];
    int b = batch[n];
    atomicAdd(&g_pool[b * HID_ + c], v);
    if (c == 0) atomicAdd(&g_cnt[b], 1.f);
}

// Final MLP: one warp per graph. [32 pooled | 15 stats] -> 32 -> 1
__global__ void k_mlp(const float* __restrict__ stats,
                      const float* __restrict__ Wm1, const float* __restrict__ bm1,
                      const float* __restrict__ Wm2, const float* __restrict__ bm2,
                      float* __restrict__ out)
{
    int b = blockIdx.x;
    int t = threadIdx.x;
    __shared__ float gv[HID_ + NF_ + 1];
    float cnt = fmaxf(g_cnt[b], 1.f);
    gv[t] = g_pool[b * HID_ + t] / cnt;
    if (t < NF_) gv[HID_ + t] = stats[b * NF_ + t];
    __syncwarp();
    float h = bm1[t];
    #pragma unroll
    for (int i = 0; i < HID_ + NF_; i++) h += gv[i] * Wm1[i * HID_ + t];
    h = fmaxf(h, 0.f);
    float o = h * Wm2[t];
    #pragma unroll
    for (int off = 16; off > 0; off >>= 1) o += __shfl_down_sync(0xffffffffu, o, off);
    if (t == 0) out[b] = o + bm2[0];
}

// ---------------- launch ----------------
extern "C" void kernel_launch(void* const* d_in, const int* in_sizes, int n_in,
                              void* d_out, int out_size)
{
    const float* x     = (const float*)d_in[0];
    const int*   ei    = (const int*)d_in[1];      // int32 (JAX x64 disabled)
    const int*   batch = (const int*)d_in[2];      // int32
    const float* stats = (const float*)d_in[3];
    const float* W1    = (const float*)d_in[4];
    const float* as1   = (const float*)d_in[5];
    const float* ad1   = (const float*)d_in[6];
    const float* b1    = (const float*)d_in[7];
    const float* W2    = (const float*)d_in[8];
    const float* as2   = (const float*)d_in[9];
    const float* ad2   = (const float*)d_in[10];
    const float* b2    = (const float*)d_in[11];
    const float* Wm1   = (const float*)d_in[12];
    const float* bm1   = (const float*)d_in[13];
    const float* Wm2   = (const float*)d_in[14];
    const float* bm2   = (const float*)d_in[15];
    float*       out   = (float*)d_out;

    const int T = 256;
    auto cdiv = [](long long a, long long b) { return (int)((a + b - 1) / b); };

    k_build_edges<<<cdiv(EP_, T), T>>>(ei);

    // ---- layer 1 ----
    k_init_layer<<<cdiv((long long)N_ * C_, T), T>>>();
    k_gemm_attn<<<N_ / 16, 128>>>(x, W1, as1, ad1);
    k_edge_fused<<<cdiv((long long)EP_ * 32, T), T>>>();
    k_norm_relu_bias<<<cdiv((long long)N_ * C_, T), T>>>(b1);

    // ---- layer 2 (gemm reads g_agg, so it runs BEFORE re-init) ----
    k_gemm_attn<<<N_ / 16, 128>>>(nullptr, W2, as2, ad2);
    k_init_layer<<<cdiv((long long)N_ * C_, T), T>>>();
    k_edge_fused<<<cdiv((long long)EP_ * 32, T), T>>>();

    // ---- pooling + MLP ----
    k_zero_pool<<<cdiv(B_ * HID_ + B_, T), T>>>();
    k_pool<<<cdiv((long long)N_ * HID_, T), T>>>(batch, b2);
    k_mlp<<<B_, HID_>>>(stats, Wm1, bm1, Wm2, bm2, out);
}

// round 7
// speedup vs baseline: 1.7635x; 1.3974x over previous
#include <cuda_runtime.h>
#include <cuda_bf16.h>
#include <cstdint>

// Problem constants (fixed by the reference)
constexpr int N_   = 50000;
constexpr int E_   = 800000;
constexpr int EP_  = E_ + N_;      // edges + self loops = 850000
constexpr int C_   = 128;          // feature dim (HEADS*HID)
constexpr int H_   = 4;            // heads
constexpr int HID_ = 32;
constexpr int B_   = 100;
constexpr int NF_  = 15;
constexpr float NEG_SLOPE = 0.2f;

// ---------------- scratch (static device globals; no allocation) ----------------
__device__ __align__(16) float g_xh[(size_t)N_ * C_];   // transformed features [N,128]
__device__ __align__(16) float g_h[(size_t)N_ * C_];    // layer-1 output (hidden)
__device__ __align__(16) float g_asrc[N_ * H_];
__device__ __align__(16) float g_adst[N_ * H_];
__device__ int   g_rowptr[N_ + 1];
__device__ int   g_cursor[N_];       // also used as degree buffer
__device__ int   g_csr_src[EP_];
__device__ __align__(16) float g_pool[B_ * HID_];
__device__ float g_cnt[B_];

// ---------------- helpers ----------------
__device__ __forceinline__ float lrelu(float x) {
    return x > 0.f ? x : NEG_SLOPE * x;
}

// ---------------- CSR build ----------------

__global__ void k_zero_pool_deg() {
    int i = blockIdx.x * blockDim.x + threadIdx.x;
    if (i < B_ * HID_) g_pool[i] = 0.f;
    if (i < B_)        g_cnt[i]  = 0.f;
    if (i < N_)        g_cursor[i] = 1;   // degree starts at 1 (self loop)
}

__global__ void k_hist(const int* __restrict__ ei) {
    int e = blockIdx.x * blockDim.x + threadIdx.x;
    if (e < E_) atomicAdd(&g_cursor[ei[E_ + e]], 1);
}

// Single-block exclusive scan of g_cursor[0..N_) into g_rowptr (rowptr[N_]=EP_).
__global__ void __launch_bounds__(1024) k_scan() {
    __shared__ int ssum[1024];
    int t = threadIdx.x;
    constexpr int PER = (N_ + 1023) / 1024;   // 49
    int lo = t * PER;
    int hi = min(lo + PER, N_);
    int s = 0;
    for (int i = lo; i < hi; i++) s += g_cursor[i];
    ssum[t] = s;
    __syncthreads();
    for (int off = 1; off < 1024; off <<= 1) {
        int u = (t >= off) ? ssum[t - off] : 0;
        __syncthreads();
        ssum[t] += u;
        __syncthreads();
    }
    int run = ssum[t] - s;     // exclusive base for this segment
    for (int i = lo; i < hi; i++) {
        g_rowptr[i] = run;
        run += g_cursor[i];
    }
    if (t == 1023) g_rowptr[N_] = ssum[1023];
}

// Self loop goes in slot 0 of each row; cursor points past it.
__global__ void k_scatter_self() {
    int n = blockIdx.x * blockDim.x + threadIdx.x;
    if (n >= N_) return;
    int r = g_rowptr[n];
    g_csr_src[r] = n;
    g_cursor[n] = r + 1;
}

__global__ void k_scatter(const int* __restrict__ ei) {
    int e = blockIdx.x * blockDim.x + threadIdx.x;
    if (e >= E_) return;
    int s = ei[e], d = ei[E_ + e];
    int pos = atomicAdd(&g_cursor[d], 1);
    g_csr_src[pos] = s;
}

// ---------------- GEMM + attention dots ----------------
// xh = X @ W ; a_src/a_dst dots. 16 rows/block, 128 threads (thread = out col).
// X==nullptr means "use g_h as input" (layer 2).
__global__ void __launch_bounds__(128) k_gemm_attn(
    const float* __restrict__ X,
    const float* __restrict__ W,
    const float* __restrict__ attS,
    const float* __restrict__ attD)
{
    __shared__ float xs[16 * 128];
    const float* Xp = X ? X : g_h;
    int row0 = blockIdx.x * 16;
    int tid  = threadIdx.x;

    const float* xb = Xp + (size_t)row0 * C_;
    #pragma unroll
    for (int r = 0; r < 16; r++) xs[r * 128 + tid] = xb[r * 128 + tid];
    __syncthreads();

    float acc[16];
    #pragma unroll
    for (int r = 0; r < 16; r++) acc[r] = 0.f;

    for (int k = 0; k < 128; k++) {
        float wv = W[k * 128 + tid];
        #pragma unroll
        for (int r = 0; r < 16; r++) acc[r] += xs[r * 128 + k] * wv;
    }

    #pragma unroll
    for (int r = 0; r < 16; r++)
        g_xh[(size_t)(row0 + r) * C_ + tid] = acc[r];

    int head = tid >> 5, lane = tid & 31;
    float as = attS[head * 32 + lane];
    float ad = attD[head * 32 + lane];
    #pragma unroll
    for (int r = 0; r < 16; r++) {
        float vs = acc[r] * as;
        float vd = acc[r] * ad;
        #pragma unroll
        for (int o = 16; o > 0; o >>= 1) {
            vs += __shfl_down_sync(0xffffffffu, vs, o);
            vd += __shfl_down_sync(0xffffffffu, vd, o);
        }
        if (lane == 0) {
            g_asrc[(row0 + r) * H_ + head] = vs;
            g_adst[(row0 + r) * H_ + head] = vd;
        }
    }
}

// ---------------- CSR aggregation: one warp per dst node, no atomics on features.
// Softmax shift-invariance: logits tiny (|e|<~10) -> no max pass; normalize at the end.
// LAYER 1: write relu(agg/denom + b1) to g_h.
// LAYER 2: head-mean via shfl, atomic into graph pool (no feature write at all).
template<int LAYER>
__global__ void __launch_bounds__(256) k_csr_agg(
    const float* __restrict__ bias,
    const int*   __restrict__ batch)
{
    int warp = (blockIdx.x * blockDim.x + threadIdx.x) >> 5;
    if (warp >= N_) return;
    int lane = threadIdx.x & 31;
    int head = lane >> 3;
    int n = warp;

    float adv = g_adst[n * H_ + head];
    int beg = g_rowptr[n];
    int end = g_rowptr[n + 1];

    float a0 = 0.f, a1 = 0.f, a2 = 0.f, a3 = 0.f, dsum = 0.f;

    int j = beg;
    // 2-deep unroll: two independent gather chains in flight
    for (; j + 1 < end; j += 2) {
        int s0 = g_csr_src[j];
        int s1 = g_csr_src[j + 1];
        float e0 = __expf(lrelu(g_asrc[s0 * H_ + head] + adv));
        float e1 = __expf(lrelu(g_asrc[s1 * H_ + head] + adv));
        float4 x0 = *(const float4*)&g_xh[(size_t)s0 * C_ + lane * 4];
        float4 x1 = *(const float4*)&g_xh[(size_t)s1 * C_ + lane * 4];
        a0 += e0 * x0.x + e1 * x1.x;
        a1 += e0 * x0.y + e1 * x1.y;
        a2 += e0 * x0.z + e1 * x1.z;
        a3 += e0 * x0.w + e1 * x1.w;
        dsum += e0 + e1;
    }
    if (j < end) {
        int s0 = g_csr_src[j];
        float e0 = __expf(lrelu(g_asrc[s0 * H_ + head] + adv));
        float4 x0 = *(const float4*)&g_xh[(size_t)s0 * C_ + lane * 4];
        a0 += e0 * x0.x; a1 += e0 * x0.y; a2 += e0 * x0.z; a3 += e0 * x0.w;
        dsum += e0;
    }

    float inv = 1.f / (dsum + 1e-16f);
    if (LAYER == 1) {
        float4 o;
        o.x = fmaxf(a0 * inv + bias[lane * 4 + 0], 0.f);
        o.y = fmaxf(a1 * inv + bias[lane * 4 + 1], 0.f);
        o.z = fmaxf(a2 * inv + bias[lane * 4 + 2], 0.f);
        o.w = fmaxf(a3 * inv + bias[lane * 4 + 3], 0.f);
        *(float4*)&g_h[(size_t)n * C_ + lane * 4] = o;
    } else {
        float v0 = a0 * inv, v1 = a1 * inv, v2 = a2 * inv, v3 = a3 * inv;
        // sum across the 4 heads: lanes l, l^8, l^16, l^24 hold the same hidden channel
        #pragma unroll
        for (int m = 8; m <= 16; m <<= 1) {
            v0 += __shfl_xor_sync(0xffffffffu, v0, m);
            v1 += __shfl_xor_sync(0xffffffffu, v1, m);
            v2 += __shfl_xor_sync(0xffffffffu, v2, m);
            v3 += __shfl_xor_sync(0xffffffffu, v3, m);
        }
        if (lane < 8) {
            int b = batch[n];
            float4 p;
            p.x = 0.25f * v0 + bias[lane * 4 + 0];
            p.y = 0.25f * v1 + bias[lane * 4 + 1];
            p.z = 0.25f * v2 + bias[lane * 4 + 2];
            p.w = 0.25f * v3 + bias[lane * 4 + 3];
            atomicAdd((float4*)&g_pool[b * HID_ + lane * 4], p);
            if (lane == 0) atomicAdd(&g_cnt[b], 1.f);
        }
    }
}

// Final MLP: one warp per graph. [32 pooled | 15 stats] -> 32 -> 1
__global__ void k_mlp(const float* __restrict__ stats,
                      const float* __restrict__ Wm1, const float* __restrict__ bm1,
                      const float* __restrict__ Wm2, const float* __restrict__ bm2,
                      float* __restrict__ out)
{
    int b = blockIdx.x;
    int t = threadIdx.x;
    __shared__ float gv[HID_ + NF_ + 1];
    float cnt = fmaxf(g_cnt[b], 1.f);
    gv[t] = g_pool[b * HID_ + t] / cnt;
    if (t < NF_) gv[HID_ + t] = stats[b * NF_ + t];
    __syncwarp();
    float h = bm1[t];
    #pragma unroll
    for (int i = 0; i < HID_ + NF_; i++) h += gv[i] * Wm1[i * HID_ + t];
    h = fmaxf(h, 0.f);
    float o = h * Wm2[t];
    #pragma unroll
    for (int off = 16; off > 0; off >>= 1) o += __shfl_down_sync(0xffffffffu, o, off);
    if (t == 0) out[b] = o + bm2[0];
}

// ---------------- launch ----------------
extern "C" void kernel_launch(void* const* d_in, const int* in_sizes, int n_in,
                              void* d_out, int out_size)
{
    const float* x     = (const float*)d_in[0];
    const int*   ei    = (const int*)d_in[1];      // int32 (JAX x64 disabled)
    const int*   batch = (const int*)d_in[2];      // int32
    const float* stats = (const float*)d_in[3];
    const float* W1    = (const float*)d_in[4];
    const float* as1   = (const float*)d_in[5];
    const float* ad1   = (const float*)d_in[6];
    const float* b1    = (const float*)d_in[7];
    const float* W2    = (const float*)d_in[8];
    const float* as2   = (const float*)d_in[9];
    const float* ad2   = (const float*)d_in[10];
    const float* b2    = (const float*)d_in[11];
    const float* Wm1   = (const float*)d_in[12];
    const float* bm1   = (const float*)d_in[13];
    const float* Wm2   = (const float*)d_in[14];
    const float* bm2   = (const float*)d_in[15];
    float*       out   = (float*)d_out;

    const int T = 256;
    auto cdiv = [](long long a, long long b) { return (int)((a + b - 1) / b); };

    // ---- CSR build (also zeroes pool/cnt) ----
    k_zero_pool_deg<<<cdiv(N_, T), T>>>();
    k_hist<<<cdiv(E_, T), T>>>(ei);
    k_scan<<<1, 1024>>>();
    k_scatter_self<<<cdiv(N_, T), T>>>();
    k_scatter<<<cdiv(E_, T), T>>>(ei);

    // ---- layer 1 ----
    k_gemm_attn<<<N_ / 16, 128>>>(x, W1, as1, ad1);
    k_csr_agg<1><<<cdiv((long long)N_ * 32, T), T>>>(b1, nullptr);

    // ---- layer 2 ----
    k_gemm_attn<<<N_ / 16, 128>>>(nullptr, W2, as2, ad2);
    k_csr_agg<2><<<cdiv((long long)N_ * 32, T), T>>>(b2, batch);

    // ---- MLP ----
    k_mlp<<<B_, HID_>>>(stats, Wm1, bm1, Wm2, bm2, out);
}